// round 4
// baseline (speedup 1.0000x reference)
#include <cuda_runtime.h>
#include <math.h>

#define NROWS 4096
#define KDIM  1024
#define NHEAD 2002
#define CUT0  2000
#define CUT1  10000
#define NTOK  50257
#define SZ0   8000
#define SZ1   40257
#define D0    256
#define D1    64

// ---------------- scratch (device globals: no allocation allowed) -----------
__device__ float g_proj0[NROWS * D0];
__device__ float g_proj1[NROWS * D1];
__device__ float g_sum_head[NROWS];
__device__ float g_sum_tail[NROWS];
__device__ int   g_idx0[NROWS];
__device__ int   g_idx1[NROWS];
__device__ int   g_cnt0, g_cnt1;

// ---------------- init / classify ------------------------------------------
__global__ void init_kernel() {
    int i = blockIdx.x * blockDim.x + threadIdx.x;
    if (i < NROWS) { g_sum_head[i] = 0.f; g_sum_tail[i] = 0.f; }
    if (i == 0) { g_cnt0 = 0; g_cnt1 = 0; }
}

__global__ void classify_kernel(const int* __restrict__ targets) {
    int i = blockIdx.x * blockDim.x + threadIdx.x;
    if (i >= NROWS) return;
    int t = targets[i];
    if (t >= CUT0 && t < CUT1) { int p = atomicAdd(&g_cnt0, 1); g_idx0[p] = i; }
    else if (t >= CUT1)        { int p = atomicAdd(&g_cnt1, 1); g_idx1[p] = i; }
}

// ---------------- projection GEMM: P = A(4096xK) @ B(K x dout) --------------
__global__ void __launch_bounds__(256) proj_kernel(
    const float* __restrict__ A, const float* __restrict__ B,
    int K, int dout, int which)
{
    __shared__ float As[64][68];   // [row][k]
    __shared__ float Bs[64][68];   // [k][n]
    float* __restrict__ P = (which == 0) ? g_proj0 : g_proj1;  // device-side symbol

    int tid = threadIdx.x;
    int tx = tid & 15, ty = tid >> 4;
    int row0 = blockIdx.x * 64;
    int nc   = blockIdx.y * 64;

    float acc[4][4] = {};
    for (int kc = 0; kc < K; kc += 64) {
        __syncthreads();
        {   // A tile: 64 rows x 64 k
            int r = tid >> 2, q = tid & 3;
            const float* ga = A + (long)(row0 + r) * K + kc;
            #pragma unroll
            for (int j = 0; j < 4; j++) {
                int c = (q + 4 * j) * 4;
                float4 v = *reinterpret_cast<const float4*>(ga + c);
                *reinterpret_cast<float4*>(&As[r][c]) = v;
            }
        }
        {   // B tile: B[k][n] natural
            int k = tid >> 2, q = tid & 3;
            const float* gb = B + (long)(kc + k) * dout + nc;
            #pragma unroll
            for (int j = 0; j < 4; j++) {
                int c = (q + 4 * j) * 4;
                float4 v = *reinterpret_cast<const float4*>(gb + c);
                *reinterpret_cast<float4*>(&Bs[k][c]) = v;
            }
        }
        __syncthreads();
        #pragma unroll
        for (int k = 0; k < 64; k++) {
            float4 b = *reinterpret_cast<float4*>(&Bs[k][tx * 4]);
            float a0 = As[ty * 4 + 0][k], a1 = As[ty * 4 + 1][k];
            float a2 = As[ty * 4 + 2][k], a3 = As[ty * 4 + 3][k];
            acc[0][0] += a0 * b.x; acc[0][1] += a0 * b.y; acc[0][2] += a0 * b.z; acc[0][3] += a0 * b.w;
            acc[1][0] += a1 * b.x; acc[1][1] += a1 * b.y; acc[1][2] += a1 * b.z; acc[1][3] += a1 * b.w;
            acc[2][0] += a2 * b.x; acc[2][1] += a2 * b.y; acc[2][2] += a2 * b.z; acc[2][3] += a2 * b.w;
            acc[3][0] += a3 * b.x; acc[3][1] += a3 * b.y; acc[3][2] += a3 * b.z; acc[3][3] += a3 * b.w;
        }
    }
    #pragma unroll
    for (int i = 0; i < 4; i++) {
        float4 v = make_float4(acc[i][0], acc[i][1], acc[i][2], acc[i][3]);
        *reinterpret_cast<float4*>(&P[(long)(row0 + ty * 4 + i) * dout + nc + tx * 4]) = v;
    }
}

// -------- fused GEMM + exp + row-sum: sums[row] += sum_n exp(A_row . B_n) ---
// which: 0 = head (A = Ain = inputs), 1 = tail0 (A = g_proj0), 2 = tail1 (A = g_proj1)
// A pointer for tails is resolved IN DEVICE CODE (never pass __device__ symbols
// from host: on GB300 ATS resolves the host shadow address and reads zeros).
__global__ void __launch_bounds__(256) expsum_kernel(
    const float* __restrict__ Ain, int K,
    const float* __restrict__ B, int ncols, int which)
{
    __shared__ float As[64][68];
    __shared__ float Bs[64][68];
    __shared__ float rowAcc[64];
    __shared__ int   rowsId[64];

    int M = NROWS;
    const int* idx = nullptr;
    const float* A = Ain;
    float* sums = g_sum_head;
    if (which == 1) { M = g_cnt0; idx = g_idx0; sums = g_sum_tail; A = g_proj0; }
    else if (which == 2) { M = g_cnt1; idx = g_idx1; sums = g_sum_tail; A = g_proj1; }

    int row0 = blockIdx.x * 64;
    if (row0 >= M) return;

    int tid = threadIdx.x;
    if (tid < 64) {
        int r = row0 + tid;
        rowsId[tid] = idx ? idx[r < M ? r : (M - 1)] : r;
        rowAcc[tid] = 0.f;
    }
    __syncthreads();

    int tx = tid & 15, ty = tid >> 4;

    for (int nc = blockIdx.y * 64; nc < ncols; nc += gridDim.y * 64) {
        float acc[4][4] = {};
        for (int kc = 0; kc < K; kc += 64) {
            __syncthreads();
            {   // A tile (gathered rows)
                int r = tid >> 2, q = tid & 3;
                const float* ga = A + (long)rowsId[r] * K + kc;
                #pragma unroll
                for (int j = 0; j < 4; j++) {
                    int c = (q + 4 * j) * 4;
                    float4 v = *reinterpret_cast<const float4*>(ga + c);
                    *reinterpret_cast<float4*>(&As[r][c]) = v;
                }
            }
            {   // B tile: B[n][k] -> Bs[k][n] transpose, zero-pad n>=ncols
                int n = tid >> 2, q = tid & 3;
                int ng = nc + n;
                #pragma unroll
                for (int j = 0; j < 4; j++) {
                    int c = (q + 4 * j) * 4;
                    float4 v = make_float4(0.f, 0.f, 0.f, 0.f);
                    if (ng < ncols)
                        v = *reinterpret_cast<const float4*>(&B[(long)ng * K + kc + c]);
                    Bs[c + 0][n] = v.x; Bs[c + 1][n] = v.y;
                    Bs[c + 2][n] = v.z; Bs[c + 3][n] = v.w;
                }
            }
            __syncthreads();
            #pragma unroll
            for (int k = 0; k < 64; k++) {
                float4 b = *reinterpret_cast<float4*>(&Bs[k][tx * 4]);
                float a0 = As[ty * 4 + 0][k], a1 = As[ty * 4 + 1][k];
                float a2 = As[ty * 4 + 2][k], a3 = As[ty * 4 + 3][k];
                acc[0][0] += a0 * b.x; acc[0][1] += a0 * b.y; acc[0][2] += a0 * b.z; acc[0][3] += a0 * b.w;
                acc[1][0] += a1 * b.x; acc[1][1] += a1 * b.y; acc[1][2] += a1 * b.z; acc[1][3] += a1 * b.w;
                acc[2][0] += a2 * b.x; acc[2][1] += a2 * b.y; acc[2][2] += a2 * b.z; acc[2][3] += a2 * b.w;
                acc[3][0] += a3 * b.x; acc[3][1] += a3 * b.y; acc[3][2] += a3 * b.z; acc[3][3] += a3 * b.w;
            }
        }
        // fused exp + per-row partial sum (|logit| <~ 8 analytically -> no max pass)
        #pragma unroll
        for (int i = 0; i < 4; i++) {
            float s = 0.f;
            #pragma unroll
            for (int j = 0; j < 4; j++)
                if (nc + tx * 4 + j < ncols) s += __expf(acc[i][j]);
            atomicAdd(&rowAcc[ty * 4 + i], s);
        }
    }
    __syncthreads();
    if (tid < 64 && row0 + tid < M)
        atomicAdd(&sums[rowsId[tid]], rowAcc[tid]);
}

// ---------------- final gather --------------------------------------------
__global__ void __launch_bounds__(256) final_kernel(
    const float* __restrict__ inputs, const int* __restrict__ targets,
    const float* __restrict__ head_W, const float* __restrict__ emb0,
    const float* __restrict__ emb1, float* __restrict__ out)
{
    int warp = (blockIdx.x * blockDim.x + threadIdx.x) >> 5;
    int lane = threadIdx.x & 31;
    if (warp >= NROWS) return;
    int row = warp;
    int t = targets[row];
    int ht = (t < CUT0) ? t : ((t < CUT1) ? CUT0 : CUT0 + 1);

    float s = 0.f;
    const float* x = inputs + (long)row * KDIM;
    const float* w = head_W + (long)ht * KDIM;
    for (int k = lane; k < KDIM; k += 32) s += x[k] * w[k];
    #pragma unroll
    for (int o = 16; o; o >>= 1) s += __shfl_xor_sync(0xffffffffu, s, o);
    float res = s - logf(g_sum_head[row]);

    if (t >= CUT0) {
        float tl = 0.f;
        if (t < CUT1) {
            const float* p = g_proj0 + (long)row * D0;
            const float* e = emb0 + (long)(t - CUT0) * D0;
            for (int k = lane; k < D0; k += 32) tl += p[k] * e[k];
        } else {
            const float* p = g_proj1 + (long)row * D1;
            const float* e = emb1 + (long)(t - CUT1) * D1;
            for (int k = lane; k < D1; k += 32) tl += p[k] * e[k];
        }
        #pragma unroll
        for (int o = 16; o; o >>= 1) tl += __shfl_xor_sync(0xffffffffu, tl, o);
        res += tl - logf(g_sum_tail[row]);
    }
    if (lane == 0) out[row] = res;
}

// -------- deterministic double-precision loss reduction ---------------------
__global__ void __launch_bounds__(1024) loss_kernel(float* __restrict__ out, int out_size) {
    __shared__ double sh[1024];
    int tid = threadIdx.x;
    double s = 0.0;
    for (int i = tid; i < NROWS; i += 1024) s += (double)out[i];
    sh[tid] = s;
    __syncthreads();
    for (int o = 512; o; o >>= 1) {
        if (tid < o) sh[tid] += sh[tid + o];
        __syncthreads();
    }
    if (tid == 0 && out_size > NROWS)
        out[out_size - 1] = (float)(-sh[0] / (double)NROWS);
}

// ---------------- launch -----------------------------------------------------
extern "C" void kernel_launch(void* const* d_in, const int* in_sizes, int n_in,
                              void* d_out, int out_size) {
    // identify inputs by element count (all distinct) -- robust to ordering
    const float* inputs = 0; const int* targets = 0; const float* head_W = 0;
    const float* emb0 = 0; const float* lin0 = 0; const float* emb1 = 0; const float* lin1 = 0;
    for (int i = 0; i < n_in; i++) {
        switch (in_sizes[i]) {
            case NROWS * KDIM:  inputs  = (const float*)d_in[i]; break;  // 4194304
            case NROWS:         targets = (const int*)  d_in[i]; break;  // 4096
            case NHEAD * KDIM:  head_W  = (const float*)d_in[i]; break;  // 2050048
            case SZ0 * D0:      emb0    = (const float*)d_in[i]; break;  // 2048000
            case KDIM * D0:     lin0    = (const float*)d_in[i]; break;  // 262144
            case SZ1 * D1:      emb1    = (const float*)d_in[i]; break;  // 2576448
            case KDIM * D1:     lin1    = (const float*)d_in[i]; break;  // 65536
        }
    }
    float* out = (float*)d_out;

    init_kernel<<<16, 256>>>();
    classify_kernel<<<16, 256>>>(targets);

    proj_kernel<<<dim3(NROWS / 64, D0 / 64), 256>>>(inputs, lin0, KDIM, D0, 0);
    proj_kernel<<<dim3(NROWS / 64, D1 / 64), 256>>>(inputs, lin1, KDIM, D1, 1);

    expsum_kernel<<<dim3(NROWS / 64, 8),  256>>>(inputs, KDIM, head_W, NHEAD, 0);
    expsum_kernel<<<dim3(NROWS / 64, 16), 256>>>(nullptr, D0,   emb0,   SZ0,   1);
    expsum_kernel<<<dim3(NROWS / 64, 16), 256>>>(nullptr, D1,   emb1,   SZ1,   2);

    final_kernel<<<(NROWS * 32) / 256, 256>>>(inputs, targets, head_W, emb0, emb1, out);
    loss_kernel<<<1, 1024>>>(out, out_size);
}

// round 5
// speedup vs baseline: 2.6058x; 2.6058x over previous
#include <cuda_runtime.h>
#include <math.h>
#include <stdint.h>

#define NROWS 4096
#define KDIM  1024
#define NHEAD 2002
#define CUT0  2000
#define CUT1  10000
#define NTOK  50257
#define SZ0   8000
#define SZ1   40257
#define D0    256
#define D1    64

// ---------------- scratch (device globals: no allocation allowed) -----------
__device__ float g_proj0[NROWS * D0];
__device__ float g_proj1[NROWS * D1];
__device__ float g_sum_head[NROWS];
__device__ float g_sum_tail[NROWS];
__device__ int   g_idx0[NROWS];
__device__ int   g_idx1[NROWS];
__device__ int   g_cnt0, g_cnt1;

// ---------------- init / classify ------------------------------------------
__global__ void init_kernel() {
    int i = blockIdx.x * blockDim.x + threadIdx.x;
    if (i < NROWS) { g_sum_head[i] = 0.f; g_sum_tail[i] = 0.f; }
    if (i == 0) { g_cnt0 = 0; g_cnt1 = 0; }
}

__global__ void classify_kernel(const int* __restrict__ targets) {
    int i = blockIdx.x * blockDim.x + threadIdx.x;
    if (i >= NROWS) return;
    int t = targets[i];
    if (t >= CUT0 && t < CUT1) { int p = atomicAdd(&g_cnt0, 1); g_idx0[p] = i; }
    else if (t >= CUT1)        { int p = atomicAdd(&g_cnt1, 1); g_idx1[p] = i; }
}

// ---------------- projection GEMM (fp32 SIMT; small share of runtime) -------
__global__ void __launch_bounds__(256) proj_kernel(
    const float* __restrict__ A, const float* __restrict__ B,
    int K, int dout, int which)
{
    __shared__ float As[64][68];
    __shared__ float Bs[64][68];
    float* __restrict__ P = (which == 0) ? g_proj0 : g_proj1;

    int tid = threadIdx.x;
    int tx = tid & 15, ty = tid >> 4;
    int row0 = blockIdx.x * 64;
    int nc   = blockIdx.y * 64;

    float acc[4][4] = {};
    for (int kc = 0; kc < K; kc += 64) {
        __syncthreads();
        {
            int r = tid >> 2, q = tid & 3;
            const float* ga = A + (long)(row0 + r) * K + kc;
            #pragma unroll
            for (int j = 0; j < 4; j++) {
                int c = (q + 4 * j) * 4;
                *reinterpret_cast<float4*>(&As[r][c]) =
                    *reinterpret_cast<const float4*>(ga + c);
            }
        }
        {
            int k = tid >> 2, q = tid & 3;
            const float* gb = B + (long)(kc + k) * dout + nc;
            #pragma unroll
            for (int j = 0; j < 4; j++) {
                int c = (q + 4 * j) * 4;
                *reinterpret_cast<float4*>(&Bs[k][c]) =
                    *reinterpret_cast<const float4*>(gb + c);
            }
        }
        __syncthreads();
        #pragma unroll
        for (int k = 0; k < 64; k++) {
            float4 b = *reinterpret_cast<float4*>(&Bs[k][tx * 4]);
            float a0 = As[ty * 4 + 0][k], a1 = As[ty * 4 + 1][k];
            float a2 = As[ty * 4 + 2][k], a3 = As[ty * 4 + 3][k];
            acc[0][0] += a0 * b.x; acc[0][1] += a0 * b.y; acc[0][2] += a0 * b.z; acc[0][3] += a0 * b.w;
            acc[1][0] += a1 * b.x; acc[1][1] += a1 * b.y; acc[1][2] += a1 * b.z; acc[1][3] += a1 * b.w;
            acc[2][0] += a2 * b.x; acc[2][1] += a2 * b.y; acc[2][2] += a2 * b.z; acc[2][3] += a2 * b.w;
            acc[3][0] += a3 * b.x; acc[3][1] += a3 * b.y; acc[3][2] += a3 * b.z; acc[3][3] += a3 * b.w;
        }
    }
    #pragma unroll
    for (int i = 0; i < 4; i++) {
        float4 v = make_float4(acc[i][0], acc[i][1], acc[i][2], acc[i][3]);
        *reinterpret_cast<float4*>(&P[(long)(row0 + ty * 4 + i) * dout + nc + tx * 4]) = v;
    }
}

// ---------------- tf32 helpers ----------------------------------------------
__device__ __forceinline__ uint32_t f2tf32(float x) {
    uint32_t r;
    asm("cvt.rna.tf32.f32 %0, %1;" : "=r"(r) : "f"(x));
    return r;
}
__device__ __forceinline__ void mma_tf32(float c[4], const uint32_t a[4], const uint32_t b[2]) {
    asm volatile(
        "mma.sync.aligned.m16n8k8.row.col.f32.tf32.tf32.f32 "
        "{%0,%1,%2,%3}, {%4,%5,%6,%7}, {%8,%9}, {%0,%1,%2,%3};"
        : "+f"(c[0]), "+f"(c[1]), "+f"(c[2]), "+f"(c[3])
        : "r"(a[0]), "r"(a[1]), "r"(a[2]), "r"(a[3]), "r"(b[0]), "r"(b[1]));
}

// ---- tensor-core fused GEMM + exp + row-sum --------------------------------
// Block tile M=128, N=64; 8 warps as 4(m) x 2(n), warp tile m32n32.
// K chunked by 32, register-prefetch of next chunk overlapped with MMA.
// which: 0 = head (A = Ain), 1 = tail0 (A = g_proj0), 2 = tail1 (A = g_proj1)
__global__ void __launch_bounds__(256) expsum_mma(
    const float* __restrict__ Ain, int K,
    const float* __restrict__ B, int ncols, int which)
{
    __shared__ uint32_t As[128][36];
    __shared__ uint32_t Bs[64][36];
    __shared__ float rowAcc[128];
    __shared__ int   rowsId[128];

    int M = NROWS;
    const int* idx = nullptr;
    const float* A = Ain;
    float* sums = g_sum_head;
    if (which == 1) { M = g_cnt0; idx = g_idx0; sums = g_sum_tail; A = g_proj0; }
    else if (which == 2) { M = g_cnt1; idx = g_idx1; sums = g_sum_tail; A = g_proj1; }

    int row0 = blockIdx.x * 128;
    if (row0 >= M) return;

    int tid = threadIdx.x;
    if (tid < 128) {
        int r = row0 + tid;
        rowsId[tid] = idx ? idx[r < M ? r : (M - 1)] : (r < M ? r : (M - 1));
        rowAcc[tid] = 0.f;
    }
    __syncthreads();

    int warp = tid >> 5, lane = tid & 31;
    int wm = (warp >> 1) * 32;           // 0,32,64,96
    int wn = (warp & 1) * 32;            // 0,32
    int grp = lane >> 2, qid = lane & 3;

    // global-load thread mapping
    int ar = tid >> 1, ah = (tid & 1) * 16;   // A: 2 thr/row, 16 k each
    int bn = tid >> 2, bk = (tid & 3) * 4;    // B: 4 thr/row(n), 4+4 k each
    const float* aRow = A + (long)rowsId[ar] * K + ah;

    for (int nc = blockIdx.y * 64; nc < ncols; nc += gridDim.y * 64) {
        float c[2][4][4];
        #pragma unroll
        for (int i = 0; i < 2; i++)
            #pragma unroll
            for (int j = 0; j < 4; j++)
                #pragma unroll
                for (int r = 0; r < 4; r++) c[i][j][r] = 0.f;

        int ng = nc + bn;
        const float* bRow = B + (long)ng * K;
        bool bval = (ng < ncols);

        // prefetch chunk 0
        float4 av[4], bv[2];
        #pragma unroll
        for (int j = 0; j < 4; j++) av[j] = *(const float4*)(aRow + j * 4);
        if (bval) {
            bv[0] = *(const float4*)(bRow + bk);
            bv[1] = *(const float4*)(bRow + bk + 16);
        } else { bv[0] = bv[1] = make_float4(0.f, 0.f, 0.f, 0.f); }

        for (int kc = 0; kc < K; kc += 32) {
            __syncthreads();   // previous chunk's MMA reads done
            // store prefetched regs -> smem (tf32)
            #pragma unroll
            for (int j = 0; j < 4; j++) {
                uint32_t* p = &As[ar][ah + j * 4];
                p[0] = f2tf32(av[j].x); p[1] = f2tf32(av[j].y);
                p[2] = f2tf32(av[j].z); p[3] = f2tf32(av[j].w);
            }
            {
                uint32_t* p0 = &Bs[bn][bk];
                p0[0] = f2tf32(bv[0].x); p0[1] = f2tf32(bv[0].y);
                p0[2] = f2tf32(bv[0].z); p0[3] = f2tf32(bv[0].w);
                uint32_t* p1 = &Bs[bn][bk + 16];
                p1[0] = f2tf32(bv[1].x); p1[1] = f2tf32(bv[1].y);
                p1[2] = f2tf32(bv[1].z); p1[3] = f2tf32(bv[1].w);
            }
            __syncthreads();

            // prefetch next chunk while MMAs run
            if (kc + 32 < K) {
                const float* an = aRow + kc + 32;
                #pragma unroll
                for (int j = 0; j < 4; j++) av[j] = *(const float4*)(an + j * 4);
                if (bval) {
                    const float* bnp = bRow + kc + 32;
                    bv[0] = *(const float4*)(bnp + bk);
                    bv[1] = *(const float4*)(bnp + bk + 16);
                }
            }

            #pragma unroll
            for (int ks = 0; ks < 4; ks++) {
                int k0 = ks * 8;
                uint32_t a[2][4], b[4][2];
                #pragma unroll
                for (int i = 0; i < 2; i++) {
                    int r = wm + i * 16 + grp;
                    a[i][0] = As[r][k0 + qid];
                    a[i][1] = As[r + 8][k0 + qid];
                    a[i][2] = As[r][k0 + qid + 4];
                    a[i][3] = As[r + 8][k0 + qid + 4];
                }
                #pragma unroll
                for (int j = 0; j < 4; j++) {
                    int n = wn + j * 8 + grp;
                    b[j][0] = Bs[n][k0 + qid];
                    b[j][1] = Bs[n][k0 + qid + 4];
                }
                #pragma unroll
                for (int i = 0; i < 2; i++)
                    #pragma unroll
                    for (int j = 0; j < 4; j++)
                        mma_tf32(c[i][j], a[i], b[j]);
            }
        }

        // epilogue: exp + row-sum (mask padded cols)
        #pragma unroll
        for (int i = 0; i < 2; i++) {
            float s0 = 0.f, s1 = 0.f;
            #pragma unroll
            for (int j = 0; j < 4; j++) {
                int col = nc + wn + j * 8 + 2 * qid;
                if (col < ncols)     { s0 += __expf(c[i][j][0]); s1 += __expf(c[i][j][2]); }
                if (col + 1 < ncols) { s0 += __expf(c[i][j][1]); s1 += __expf(c[i][j][3]); }
            }
            s0 += __shfl_xor_sync(0xffffffffu, s0, 1);
            s0 += __shfl_xor_sync(0xffffffffu, s0, 2);
            s1 += __shfl_xor_sync(0xffffffffu, s1, 1);
            s1 += __shfl_xor_sync(0xffffffffu, s1, 2);
            if (qid == 0) {
                atomicAdd(&rowAcc[wm + i * 16 + grp], s0);
                atomicAdd(&rowAcc[wm + i * 16 + grp + 8], s1);
            }
        }
    }
    __syncthreads();
    if (tid < 128 && row0 + tid < M)
        atomicAdd(&sums[rowsId[tid]], rowAcc[tid]);
}

// ---------------- final gather ----------------------------------------------
__global__ void __launch_bounds__(256) final_kernel(
    const float* __restrict__ inputs, const int* __restrict__ targets,
    const float* __restrict__ head_W, const float* __restrict__ emb0,
    const float* __restrict__ emb1, float* __restrict__ out)
{
    int warp = (blockIdx.x * blockDim.x + threadIdx.x) >> 5;
    int lane = threadIdx.x & 31;
    if (warp >= NROWS) return;
    int row = warp;
    int t = targets[row];
    int ht = (t < CUT0) ? t : ((t < CUT1) ? CUT0 : CUT0 + 1);

    float s = 0.f;
    const float* x = inputs + (long)row * KDIM;
    const float* w = head_W + (long)ht * KDIM;
    for (int k = lane; k < KDIM; k += 32) s += x[k] * w[k];
    #pragma unroll
    for (int o = 16; o; o >>= 1) s += __shfl_xor_sync(0xffffffffu, s, o);
    float res = s - logf(g_sum_head[row]);

    if (t >= CUT0) {
        float tl = 0.f;
        if (t < CUT1) {
            const float* p = g_proj0 + (long)row * D0;
            const float* e = emb0 + (long)(t - CUT0) * D0;
            for (int k = lane; k < D0; k += 32) tl += p[k] * e[k];
        } else {
            const float* p = g_proj1 + (long)row * D1;
            const float* e = emb1 + (long)(t - CUT1) * D1;
            for (int k = lane; k < D1; k += 32) tl += p[k] * e[k];
        }
        #pragma unroll
        for (int o = 16; o; o >>= 1) tl += __shfl_xor_sync(0xffffffffu, tl, o);
        res += tl - logf(g_sum_tail[row]);
    }
    if (lane == 0) out[row] = res;
}

// -------- deterministic double-precision loss reduction ---------------------
__global__ void __launch_bounds__(1024) loss_kernel(float* __restrict__ out, int out_size) {
    __shared__ double sh[1024];
    int tid = threadIdx.x;
    double s = 0.0;
    for (int i = tid; i < NROWS; i += 1024) s += (double)out[i];
    sh[tid] = s;
    __syncthreads();
    for (int o = 512; o; o >>= 1) {
        if (tid < o) sh[tid] += sh[tid + o];
        __syncthreads();
    }
    if (tid == 0 && out_size > NROWS)
        out[out_size - 1] = (float)(-sh[0] / (double)NROWS);
}

// ---------------- launch -----------------------------------------------------
extern "C" void kernel_launch(void* const* d_in, const int* in_sizes, int n_in,
                              void* d_out, int out_size) {
    const float* inputs = 0; const int* targets = 0; const float* head_W = 0;
    const float* emb0 = 0; const float* lin0 = 0; const float* emb1 = 0; const float* lin1 = 0;
    for (int i = 0; i < n_in; i++) {
        switch (in_sizes[i]) {
            case NROWS * KDIM:  inputs  = (const float*)d_in[i]; break;
            case NROWS:         targets = (const int*)  d_in[i]; break;
            case NHEAD * KDIM:  head_W  = (const float*)d_in[i]; break;
            case SZ0 * D0:      emb0    = (const float*)d_in[i]; break;
            case KDIM * D0:     lin0    = (const float*)d_in[i]; break;
            case SZ1 * D1:      emb1    = (const float*)d_in[i]; break;
            case KDIM * D1:     lin1    = (const float*)d_in[i]; break;
        }
    }
    float* out = (float*)d_out;

    init_kernel<<<16, 256>>>();
    classify_kernel<<<16, 256>>>(targets);

    proj_kernel<<<dim3(NROWS / 64, D0 / 64), 256>>>(inputs, lin0, KDIM, D0, 0);
    proj_kernel<<<dim3(NROWS / 64, D1 / 64), 256>>>(inputs, lin1, KDIM, D1, 1);

    // tensor-core fused logits+expsum (M blocks of 128; dead blocks exit fast)
    expsum_mma<<<dim3(32, 32), 256>>>(inputs, KDIM, head_W, NHEAD, 0);
    expsum_mma<<<dim3(32, 32), 256>>>(nullptr, D0,   emb0,   SZ0,   1);
    expsum_mma<<<dim3(32, 32), 256>>>(nullptr, D1,   emb1,   SZ1,   2);

    final_kernel<<<(NROWS * 32) / 256, 256>>>(inputs, targets, head_W, emb0, emb1, out);
    loss_kernel<<<1, 1024>>>(out, out_size);
}